// round 2
// baseline (speedup 1.0000x reference)
#include <cuda_runtime.h>
#include <cuda_bf16.h>
#include <cstdint>

#define N_NODES 100000
#define N_EDGES 1600000
#define D_IN    256
#define D_OUT   128

// Scratch for support = x @ W  (51.2 MB). __device__ global: allowed (no alloc).
__device__ float g_support[(size_t)N_NODES * D_OUT];

// ---------------------------------------------------------------------------
// Kernel A: support = x @ W   (M=100000, K=256, N=128)
// BM=64, BN=128, BK=16, 256 threads, 8x4 register tile per thread.
// ---------------------------------------------------------------------------
__global__ __launch_bounds__(256) void gemm_kernel(const float* __restrict__ x,
                                                   const float* __restrict__ W) {
    __shared__ float As[16][68];   // [k][row], padded stride 68 (16B-aligned, fewer bank conflicts)
    __shared__ float Bs[16][128];  // [k][col]

    const int tid = threadIdx.x;
    const int block_row = blockIdx.x * 64;
    const int tx = tid & 31;       // 32 column groups of 4
    const int ty = tid >> 5;       // 8 row groups of 8

    // A-load mapping: each thread loads one float4 of x
    const int lr = tid >> 2;             // row within tile 0..63
    const int lk = (tid & 3) * 4;        // k offset 0,4,8,12
    // B-load mapping: each thread loads two float4 rows of W
    const int bk = tid >> 5;             // 0..7
    const int bc = (tid & 31) * 4;       // col 0..124

    float acc[8][4];
#pragma unroll
    for (int r = 0; r < 8; ++r)
#pragma unroll
        for (int c = 0; c < 4; ++c) acc[r][c] = 0.0f;

    const int grow = block_row + lr;
    const bool arow_ok = (grow < N_NODES);

    for (int k0 = 0; k0 < D_IN; k0 += 16) {
        // load A tile (transposed into As[k][row])
        float4 av = arow_ok ? *(const float4*)(x + (size_t)grow * D_IN + k0 + lk)
                            : make_float4(0.f, 0.f, 0.f, 0.f);
        As[lk + 0][lr] = av.x;
        As[lk + 1][lr] = av.y;
        As[lk + 2][lr] = av.z;
        As[lk + 3][lr] = av.w;
        // load B tile
        *(float4*)&Bs[bk][bc]     = *(const float4*)(W + (size_t)(k0 + bk) * D_OUT + bc);
        *(float4*)&Bs[bk + 8][bc] = *(const float4*)(W + (size_t)(k0 + bk + 8) * D_OUT + bc);
        __syncthreads();

#pragma unroll
        for (int kk = 0; kk < 16; ++kk) {
            float a[8], b[4];
            float4 a0 = *(const float4*)&As[kk][ty * 8];
            float4 a1 = *(const float4*)&As[kk][ty * 8 + 4];
            float4 bv = *(const float4*)&Bs[kk][tx * 4];
            a[0] = a0.x; a[1] = a0.y; a[2] = a0.z; a[3] = a0.w;
            a[4] = a1.x; a[5] = a1.y; a[6] = a1.z; a[7] = a1.w;
            b[0] = bv.x; b[1] = bv.y; b[2] = bv.z; b[3] = bv.w;
#pragma unroll
            for (int r = 0; r < 8; ++r)
#pragma unroll
                for (int c = 0; c < 4; ++c)
                    acc[r][c] = fmaf(a[r], b[c], acc[r][c]);
        }
        __syncthreads();
    }

    // epilogue: write support
#pragma unroll
    for (int r = 0; r < 8; ++r) {
        int orow = block_row + ty * 8 + r;
        if (orow < N_NODES) {
            float4 v = make_float4(acc[r][0], acc[r][1], acc[r][2], acc[r][3]);
            *(float4*)(g_support + (size_t)orow * D_OUT + tx * 4) = v;
        }
    }
}

// ---------------------------------------------------------------------------
// Kernel B: out[n][d] = b[d]  (bias broadcast init; d_out is poisoned)
// ---------------------------------------------------------------------------
__global__ __launch_bounds__(256) void bias_init_kernel(const float* __restrict__ b,
                                                        float* __restrict__ out) {
    int i = blockIdx.x * blockDim.x + threadIdx.x;   // float4 index
    if (i < N_NODES * (D_OUT / 4)) {
        float4 bv = ((const float4*)b)[i & (D_OUT / 4 - 1)];
        ((float4*)out)[i] = bv;
    }
}

// ---------------------------------------------------------------------------
// Kernel C: warp-per-edge gather + scale + vector scatter-add.
// Each lane handles 4 floats (128 / 32 lanes). red.global.add.v4.f32 (sm_90+)
// quarters the atomic op count vs scalar atomicAdd.
// ---------------------------------------------------------------------------
__global__ __launch_bounds__(256) void scatter_kernel(const int* __restrict__ esrc,
                                                      const int* __restrict__ edst,
                                                      const float* __restrict__ ew,
                                                      float* __restrict__ out) {
    const int e    = (blockIdx.x * blockDim.x + threadIdx.x) >> 5;
    const int lane = threadIdx.x & 31;
    if (e >= N_EDGES) return;

    const int   s = __ldg(&esrc[e]);
    const int   d = __ldg(&edst[e]);
    const float w = __ldg(&ew[e]);

    float4 v = *((const float4*)g_support + (size_t)s * (D_OUT / 4) + lane);
    v.x *= w; v.y *= w; v.z *= w; v.w *= w;

    float4* op = (float4*)out + (size_t)d * (D_OUT / 4) + lane;
    asm volatile("red.global.add.v4.f32 [%0], {%1, %2, %3, %4};"
                 :: "l"(op), "f"(v.x), "f"(v.y), "f"(v.z), "f"(v.w)
                 : "memory");
}

// ---------------------------------------------------------------------------
// Launch: inputs per metadata order: x, edge_src, edge_dst, edge_w, W, b
// ---------------------------------------------------------------------------
extern "C" void kernel_launch(void* const* d_in, const int* in_sizes, int n_in,
                              void* d_out, int out_size) {
    const float* x    = (const float*)d_in[0];
    const int*   esrc = (const int*)d_in[1];
    const int*   edst = (const int*)d_in[2];
    const float* ew   = (const float*)d_in[3];
    const float* W    = (const float*)d_in[4];
    const float* b    = (const float*)d_in[5];
    float* out = (float*)d_out;

    // A: GEMM into g_support
    int gemm_blocks = (N_NODES + 63) / 64;   // 1563
    gemm_kernel<<<gemm_blocks, 256>>>(x, W);

    // B: out = bias
    int init_elems  = N_NODES * (D_OUT / 4);          // 3.2M float4
    int init_blocks = (init_elems + 255) / 256;
    bias_init_kernel<<<init_blocks, 256>>>(b, out);

    // C: scatter-add (warp per edge)
    long long total_threads = (long long)N_EDGES * 32;
    int scat_blocks = (int)((total_threads + 255) / 256);  // 200000
    scatter_kernel<<<scat_blocks, 256>>>(esrc, edst, ew, out);
}

// round 3
// speedup vs baseline: 1.1767x; 1.1767x over previous
#include <cuda_runtime.h>
#include <cuda_bf16.h>
#include <cstdint>

#define N_NODES 100000
#define N_EDGES 1600000
#define D_IN    256
#define D_OUT   128

#define SCAN_BLOCK 1024
#define N_SCAN_BLOCKS ((N_NODES + SCAN_BLOCK - 1) / SCAN_BLOCK)   // 98

// Device scratch (static allocations are allowed; no cudaMalloc anywhere).
__device__ float g_support[(size_t)N_NODES * D_OUT];   // 51.2 MB
__device__ int   g_count[N_NODES];
__device__ int   g_offsets[N_NODES + 1];
__device__ int   g_cursor[N_NODES];
__device__ int   g_bsum[N_SCAN_BLOCKS];
__device__ int2  g_sw[N_EDGES];                        // packed (src, bits(w))

// ---------------------------------------------------------------------------
// GEMM: support = x @ W.  BM=128, BN=128, BK=8, 256 threads, 8x8 reg tile.
// ---------------------------------------------------------------------------
__global__ __launch_bounds__(256, 2) void gemm_kernel(const float* __restrict__ x,
                                                      const float* __restrict__ W) {
    __shared__ float As[8][132];    // [k][row], padded
    __shared__ float Bs[8][128];    // [k][col]

    const int tid = threadIdx.x;
    const int block_row = blockIdx.x * 128;
    const int tx = tid & 15;        // 16 col groups of 8
    const int ty = tid >> 4;        // 16 row groups of 8

    // A load: each thread one float4. row 0..127, k-offset 0 or 4
    const int lr = tid >> 1;
    const int lk = (tid & 1) * 4;
    // B load: each thread one float4. row 0..7, col group
    const int bk = tid >> 5;
    const int bc = (tid & 31) * 4;

    float acc[8][8];
#pragma unroll
    for (int r = 0; r < 8; ++r)
#pragma unroll
        for (int c = 0; c < 8; ++c) acc[r][c] = 0.0f;

    const int grow = block_row + lr;
    const bool arow_ok = (grow < N_NODES);
    const float4* xrow = (const float4*)(x + (size_t)grow * D_IN);

    for (int k0 = 0; k0 < D_IN; k0 += 8) {
        float4 av = arow_ok ? xrow[(k0 + lk) >> 2] : make_float4(0.f, 0.f, 0.f, 0.f);
        As[lk + 0][lr] = av.x;
        As[lk + 1][lr] = av.y;
        As[lk + 2][lr] = av.z;
        As[lk + 3][lr] = av.w;
        *(float4*)&Bs[bk][bc] = *(const float4*)(W + (size_t)(k0 + bk) * D_OUT + bc);
        __syncthreads();

#pragma unroll
        for (int kk = 0; kk < 8; ++kk) {
            float a[8], b[8];
            float4 a0 = *(const float4*)&As[kk][ty * 8];
            float4 a1 = *(const float4*)&As[kk][ty * 8 + 4];
            float4 b0 = *(const float4*)&Bs[kk][tx * 8];
            float4 b1 = *(const float4*)&Bs[kk][tx * 8 + 4];
            a[0] = a0.x; a[1] = a0.y; a[2] = a0.z; a[3] = a0.w;
            a[4] = a1.x; a[5] = a1.y; a[6] = a1.z; a[7] = a1.w;
            b[0] = b0.x; b[1] = b0.y; b[2] = b0.z; b[3] = b0.w;
            b[4] = b1.x; b[5] = b1.y; b[6] = b1.z; b[7] = b1.w;
#pragma unroll
            for (int r = 0; r < 8; ++r)
#pragma unroll
                for (int c = 0; c < 8; ++c)
                    acc[r][c] = fmaf(a[r], b[c], acc[r][c]);
        }
        __syncthreads();
    }

#pragma unroll
    for (int r = 0; r < 8; ++r) {
        int orow = block_row + ty * 8 + r;
        if (orow < N_NODES) {
            float* op = g_support + (size_t)orow * D_OUT + tx * 8;
            *(float4*)(op)     = make_float4(acc[r][0], acc[r][1], acc[r][2], acc[r][3]);
            *(float4*)(op + 4) = make_float4(acc[r][4], acc[r][5], acc[r][6], acc[r][7]);
        }
    }
}

// ---------------------------------------------------------------------------
// CSR-by-dst build
// ---------------------------------------------------------------------------
__global__ void zero_kernel() {
    int i = blockIdx.x * blockDim.x + threadIdx.x;
    if (i < N_NODES) g_count[i] = 0;
}

__global__ void hist_kernel(const int* __restrict__ edst) {
    int e = blockIdx.x * blockDim.x + threadIdx.x;
    if (e < N_EDGES) atomicAdd(&g_count[edst[e]], 1);
}

__global__ __launch_bounds__(SCAN_BLOCK) void scan1_kernel() {
    __shared__ int sh[SCAN_BLOCK];
    int t = threadIdx.x;
    int idx = blockIdx.x * SCAN_BLOCK + t;
    int v = (idx < N_NODES) ? g_count[idx] : 0;
    sh[t] = v;
    __syncthreads();
#pragma unroll
    for (int off = 1; off < SCAN_BLOCK; off <<= 1) {
        int add = (t >= off) ? sh[t - off] : 0;
        __syncthreads();
        sh[t] += add;
        __syncthreads();
    }
    int incl = sh[t];
    if (idx < N_NODES) g_offsets[idx] = incl - v;       // exclusive within block
    if (t == SCAN_BLOCK - 1) g_bsum[blockIdx.x] = incl; // block total
}

__global__ void scan2_kernel() {
    __shared__ int sh[N_SCAN_BLOCKS];
    int t = threadIdx.x;
    if (t < N_SCAN_BLOCKS) sh[t] = g_bsum[t];
    __syncthreads();
    if (t == 0) {
        int acc = 0;
#pragma unroll 1
        for (int i = 0; i < N_SCAN_BLOCKS; ++i) { int v = sh[i]; sh[i] = acc; acc += v; }
    }
    __syncthreads();
    if (t < N_SCAN_BLOCKS) g_bsum[t] = sh[t];
}

__global__ void scan3_kernel() {
    int idx = blockIdx.x * blockDim.x + threadIdx.x;
    if (idx < N_NODES) {
        int off = g_offsets[idx] + g_bsum[idx / SCAN_BLOCK];
        g_offsets[idx] = off;
        g_cursor[idx]  = off;
    }
    if (idx == 0) g_offsets[N_NODES] = N_EDGES;
}

__global__ void place_kernel(const int* __restrict__ esrc,
                             const int* __restrict__ edst,
                             const float* __restrict__ ew) {
    int e = blockIdx.x * blockDim.x + threadIdx.x;
    if (e >= N_EDGES) return;
    int d = edst[e];
    int pos = atomicAdd(&g_cursor[d], 1);
    g_sw[pos] = make_int2(esrc[e], __float_as_int(ew[e]));
}

// ---------------------------------------------------------------------------
// Pull: warp per dst node. out[n] = b + sum_e w_e * support[src_e]. No atomics.
// ---------------------------------------------------------------------------
__global__ __launch_bounds__(256) void pull_kernel(const float* __restrict__ b,
                                                   float* __restrict__ out) {
    const int n    = (blockIdx.x * blockDim.x + threadIdx.x) >> 5;
    const int lane = threadIdx.x & 31;
    if (n >= N_NODES) return;

    const int start = g_offsets[n];
    const int end   = g_offsets[n + 1];

    float4 acc0 = make_float4(0.f, 0.f, 0.f, 0.f);
    float4 acc1 = make_float4(0.f, 0.f, 0.f, 0.f);
    const float4* sup = (const float4*)g_support;

    int j = start;
    for (; j + 1 < end; j += 2) {
        int2 sw0 = g_sw[j];
        int2 sw1 = g_sw[j + 1];
        float w0 = __int_as_float(sw0.y);
        float w1 = __int_as_float(sw1.y);
        float4 v0 = sup[(size_t)sw0.x * (D_OUT / 4) + lane];
        float4 v1 = sup[(size_t)sw1.x * (D_OUT / 4) + lane];
        acc0.x = fmaf(w0, v0.x, acc0.x); acc0.y = fmaf(w0, v0.y, acc0.y);
        acc0.z = fmaf(w0, v0.z, acc0.z); acc0.w = fmaf(w0, v0.w, acc0.w);
        acc1.x = fmaf(w1, v1.x, acc1.x); acc1.y = fmaf(w1, v1.y, acc1.y);
        acc1.z = fmaf(w1, v1.z, acc1.z); acc1.w = fmaf(w1, v1.w, acc1.w);
    }
    if (j < end) {
        int2 sw0 = g_sw[j];
        float w0 = __int_as_float(sw0.y);
        float4 v0 = sup[(size_t)sw0.x * (D_OUT / 4) + lane];
        acc0.x = fmaf(w0, v0.x, acc0.x); acc0.y = fmaf(w0, v0.y, acc0.y);
        acc0.z = fmaf(w0, v0.z, acc0.z); acc0.w = fmaf(w0, v0.w, acc0.w);
    }

    float4 bv = ((const float4*)b)[lane];
    float4 r;
    r.x = acc0.x + acc1.x + bv.x;
    r.y = acc0.y + acc1.y + bv.y;
    r.z = acc0.z + acc1.z + bv.z;
    r.w = acc0.w + acc1.w + bv.w;
    ((float4*)out)[(size_t)n * (D_OUT / 4) + lane] = r;
}

// ---------------------------------------------------------------------------
// Launch. Inputs: x, edge_src, edge_dst, edge_w, W, b
// ---------------------------------------------------------------------------
extern "C" void kernel_launch(void* const* d_in, const int* in_sizes, int n_in,
                              void* d_out, int out_size) {
    const float* x    = (const float*)d_in[0];
    const int*   esrc = (const int*)d_in[1];
    const int*   edst = (const int*)d_in[2];
    const float* ew   = (const float*)d_in[3];
    const float* W    = (const float*)d_in[4];
    const float* b    = (const float*)d_in[5];
    float* out = (float*)d_out;

    // GEMM into g_support
    gemm_kernel<<<(N_NODES + 127) / 128, 256>>>(x, W);

    // CSR-by-dst build
    zero_kernel<<<(N_NODES + 255) / 256, 256>>>();
    hist_kernel<<<(N_EDGES + 255) / 256, 256>>>(edst);
    scan1_kernel<<<N_SCAN_BLOCKS, SCAN_BLOCK>>>();
    scan2_kernel<<<1, 128>>>();
    scan3_kernel<<<(N_NODES + 255) / 256, 256>>>();
    place_kernel<<<(N_EDGES + 255) / 256, 256>>>(esrc, edst, ew);

    // Pull + bias (one warp per node)
    long long pull_threads = (long long)N_NODES * 32;
    pull_kernel<<<(int)((pull_threads + 255) / 256), 256>>>(b, out);
}

// round 4
// speedup vs baseline: 1.2390x; 1.0529x over previous
#include <cuda_runtime.h>
#include <cuda_bf16.h>
#include <cstdint>

#define N_NODES 100000
#define N_EDGES 1600000
#define D_IN    256
#define D_OUT   128

#define SCAN_BLOCK 1024
#define N_SCAN_BLOCKS ((N_NODES + SCAN_BLOCK - 1) / SCAN_BLOCK)   // 98

// Device scratch (static __device__ arrays only; no allocation anywhere).
__device__ float g_support[(size_t)N_NODES * D_OUT];   // 51.2 MB
__device__ int   g_count[N_NODES];
__device__ int   g_offsets[N_NODES + 1];
__device__ int   g_cursor[N_NODES];
__device__ int   g_bsum[N_SCAN_BLOCKS];
__device__ int2  g_sw[N_EDGES];                        // packed (src, bits(w))

// ---------------------------------------------------------------------------
// cp.async helpers
// ---------------------------------------------------------------------------
__device__ __forceinline__ void cp_async16(void* smem_dst, const void* gmem_src) {
    uint32_t s = (uint32_t)__cvta_generic_to_shared(smem_dst);
    asm volatile("cp.async.ca.shared.global [%0], [%1], 16;" :: "r"(s), "l"(gmem_src));
}
__device__ __forceinline__ void cp_async_commit() {
    asm volatile("cp.async.commit_group;");
}
__device__ __forceinline__ void cp_async_wait_all() {
    asm volatile("cp.async.wait_group 0;");
}

// ---------------------------------------------------------------------------
// GEMM: support = x @ W.  BM=128, BN=128, BK=8, 256 threads, 8x8 reg tile.
// Double-buffered smem: next B tile via cp.async, next A tile staged in regs,
// both issued BEFORE the compute block so DRAM latency overlaps the FFMAs.
// ---------------------------------------------------------------------------
__global__ __launch_bounds__(256) void gemm_kernel(const float* __restrict__ x,
                                                   const float* __restrict__ W) {
    __shared__ float As[2][8][132];    // [buf][k][row], row-padded, 16B-aligned rows
    __shared__ float Bs[2][8][128];    // [buf][k][col]

    const int tid = threadIdx.x;
    const int block_row = blockIdx.x * 128;
    const int tx = tid & 15;        // 16 col groups of 8
    const int ty = tid >> 4;        // 16 row groups of 8

    // A load: one float4 per thread. row 0..127, k offset 0 or 4
    const int lr = tid >> 1;
    const int lk = (tid & 1) * 4;
    // B load: one float4 per thread. k-row 0..7, col
    const int bk = tid >> 5;
    const int bc = (tid & 31) * 4;

    float acc[8][8];
#pragma unroll
    for (int r = 0; r < 8; ++r)
#pragma unroll
        for (int c = 0; c < 8; ++c) acc[r][c] = 0.0f;

    const int grow = block_row + lr;
    const bool arow_ok = (grow < N_NODES);
    const float* xrow = x + (size_t)grow * D_IN;

    // ---- prologue: tile 0 ----
    float4 av = arow_ok ? __ldg((const float4*)(xrow + lk))
                        : make_float4(0.f, 0.f, 0.f, 0.f);
    cp_async16(&Bs[0][bk][bc], W + (size_t)bk * D_OUT + bc);
    cp_async_commit();
    As[0][lk + 0][lr] = av.x;
    As[0][lk + 1][lr] = av.y;
    As[0][lk + 2][lr] = av.z;
    As[0][lk + 3][lr] = av.w;
    cp_async_wait_all();
    __syncthreads();

    int buf = 0;
#pragma unroll 1
    for (int k0 = 0; k0 < D_IN; k0 += 8) {
        const int nxt = buf ^ 1;
        const bool has_next = (k0 + 8) < D_IN;
        float4 av2;
        if (has_next) {
            av2 = arow_ok ? __ldg((const float4*)(xrow + k0 + 8 + lk))
                          : make_float4(0.f, 0.f, 0.f, 0.f);
            cp_async16(&Bs[nxt][bk][bc], W + (size_t)(k0 + 8 + bk) * D_OUT + bc);
            cp_async_commit();
        }

#pragma unroll
        for (int kk = 0; kk < 8; ++kk) {
            float a[8], b[8];
            float4 a0 = *(const float4*)&As[buf][kk][ty * 8];
            float4 a1 = *(const float4*)&As[buf][kk][ty * 8 + 4];
            float4 b0 = *(const float4*)&Bs[buf][kk][tx * 8];
            float4 b1 = *(const float4*)&Bs[buf][kk][tx * 8 + 4];
            a[0] = a0.x; a[1] = a0.y; a[2] = a0.z; a[3] = a0.w;
            a[4] = a1.x; a[5] = a1.y; a[6] = a1.z; a[7] = a1.w;
            b[0] = b0.x; b[1] = b0.y; b[2] = b0.z; b[3] = b0.w;
            b[4] = b1.x; b[5] = b1.y; b[6] = b1.z; b[7] = b1.w;
#pragma unroll
            for (int r = 0; r < 8; ++r)
#pragma unroll
                for (int c = 0; c < 8; ++c)
                    acc[r][c] = fmaf(a[r], b[c], acc[r][c]);
        }

        if (has_next) {
            As[nxt][lk + 0][lr] = av2.x;
            As[nxt][lk + 1][lr] = av2.y;
            As[nxt][lk + 2][lr] = av2.z;
            As[nxt][lk + 3][lr] = av2.w;
            cp_async_wait_all();
            __syncthreads();
        }
        buf = nxt;
    }

#pragma unroll
    for (int r = 0; r < 8; ++r) {
        int orow = block_row + ty * 8 + r;
        if (orow < N_NODES) {
            float* op = g_support + (size_t)orow * D_OUT + tx * 8;
            *(float4*)(op)     = make_float4(acc[r][0], acc[r][1], acc[r][2], acc[r][3]);
            *(float4*)(op + 4) = make_float4(acc[r][4], acc[r][5], acc[r][6], acc[r][7]);
        }
    }
}

// ---------------------------------------------------------------------------
// CSR-by-dst build
// ---------------------------------------------------------------------------
__global__ void zero_kernel() {
    int i = blockIdx.x * blockDim.x + threadIdx.x;
    if (i < N_NODES) g_count[i] = 0;
}

__global__ void hist_kernel(const int* __restrict__ edst) {
    int e4 = blockIdx.x * blockDim.x + threadIdx.x;
    if (e4 < N_EDGES / 4) {
        int4 d = ((const int4*)edst)[e4];
        atomicAdd(&g_count[d.x], 1);
        atomicAdd(&g_count[d.y], 1);
        atomicAdd(&g_count[d.z], 1);
        atomicAdd(&g_count[d.w], 1);
    }
}

__global__ __launch_bounds__(SCAN_BLOCK) void scan1_kernel() {
    __shared__ int warp_sums[32];
    const int t = threadIdx.x;
    const int idx = blockIdx.x * SCAN_BLOCK + t;
    const int lane = t & 31;
    const int wrp  = t >> 5;
    int v = (idx < N_NODES) ? g_count[idx] : 0;
    int incl = v;
#pragma unroll
    for (int off = 1; off < 32; off <<= 1) {
        int n = __shfl_up_sync(0xffffffffu, incl, off);
        if (lane >= off) incl += n;
    }
    if (lane == 31) warp_sums[wrp] = incl;
    __syncthreads();
    if (t < 32) {
        int s = warp_sums[t];
        int si = s;
#pragma unroll
        for (int off = 1; off < 32; off <<= 1) {
            int n = __shfl_up_sync(0xffffffffu, si, off);
            if (t >= off) si += n;
        }
        warp_sums[t] = si - s;   // exclusive warp prefix
    }
    __syncthreads();
    int excl = incl - v + warp_sums[wrp];
    if (idx < N_NODES) g_offsets[idx] = excl;
    if (t == SCAN_BLOCK - 1) g_bsum[blockIdx.x] = excl + v;
}

__global__ void scan2_kernel() {
    __shared__ int ws[4];
    const int t = threadIdx.x;          // 128 threads
    const int lane = t & 31, wrp = t >> 5;
    int v = (t < N_SCAN_BLOCKS) ? g_bsum[t] : 0;
    int incl = v;
#pragma unroll
    for (int off = 1; off < 32; off <<= 1) {
        int n = __shfl_up_sync(0xffffffffu, incl, off);
        if (lane >= off) incl += n;
    }
    if (lane == 31) ws[wrp] = incl;
    __syncthreads();
    int add = 0;
#pragma unroll
    for (int w = 0; w < 4; ++w) add += (w < wrp) ? ws[w] : 0;
    if (t < N_SCAN_BLOCKS) g_bsum[t] = incl - v + add;   // exclusive
}

__global__ void scan3_kernel() {
    int idx = blockIdx.x * blockDim.x + threadIdx.x;
    if (idx < N_NODES) {
        int off = g_offsets[idx] + g_bsum[idx / SCAN_BLOCK];
        g_offsets[idx] = off;
        g_cursor[idx]  = off;
    }
    if (idx == 0) g_offsets[N_NODES] = N_EDGES;
}

__global__ void place_kernel(const int* __restrict__ esrc,
                             const int* __restrict__ edst,
                             const float* __restrict__ ew) {
    int e = blockIdx.x * blockDim.x + threadIdx.x;
    if (e >= N_EDGES) return;
    int d = edst[e];
    int pos = atomicAdd(&g_cursor[d], 1);
    g_sw[pos] = make_int2(esrc[e], __float_as_int(ew[e]));
}

// ---------------------------------------------------------------------------
// Pull: warp per dst node, 4 gathers in flight (MLP=4). No atomics.
// out[n] = b + sum_e w_e * support[src_e]
// ---------------------------------------------------------------------------
__global__ __launch_bounds__(256) void pull_kernel(const float* __restrict__ b,
                                                   float* __restrict__ out) {
    const int n    = (blockIdx.x * blockDim.x + threadIdx.x) >> 5;
    const int lane = threadIdx.x & 31;
    if (n >= N_NODES) return;

    const int start = __ldg(&g_offsets[n]);
    const int end   = __ldg(&g_offsets[n + 1]);

    float4 acc0 = make_float4(0.f, 0.f, 0.f, 0.f);
    float4 acc1 = make_float4(0.f, 0.f, 0.f, 0.f);
    const float4* sup = (const float4*)g_support;

    int j = start;
    for (; j + 3 < end; j += 4) {
        int2 sw0 = __ldg(&g_sw[j]);
        int2 sw1 = __ldg(&g_sw[j + 1]);
        int2 sw2 = __ldg(&g_sw[j + 2]);
        int2 sw3 = __ldg(&g_sw[j + 3]);
        float4 v0 = __ldg(sup + (size_t)sw0.x * (D_OUT / 4) + lane);
        float4 v1 = __ldg(sup + (size_t)sw1.x * (D_OUT / 4) + lane);
        float4 v2 = __ldg(sup + (size_t)sw2.x * (D_OUT / 4) + lane);
        float4 v3 = __ldg(sup + (size_t)sw3.x * (D_OUT / 4) + lane);
        float w0 = __int_as_float(sw0.y), w1 = __int_as_float(sw1.y);
        float w2 = __int_as_float(sw2.y), w3 = __int_as_float(sw3.y);
        acc0.x = fmaf(w0, v0.x, acc0.x); acc0.y = fmaf(w0, v0.y, acc0.y);
        acc0.z = fmaf(w0, v0.z, acc0.z); acc0.w = fmaf(w0, v0.w, acc0.w);
        acc1.x = fmaf(w1, v1.x, acc1.x); acc1.y = fmaf(w1, v1.y, acc1.y);
        acc1.z = fmaf(w1, v1.z, acc1.z); acc1.w = fmaf(w1, v1.w, acc1.w);
        acc0.x = fmaf(w2, v2.x, acc0.x); acc0.y = fmaf(w2, v2.y, acc0.y);
        acc0.z = fmaf(w2, v2.z, acc0.z); acc0.w = fmaf(w2, v2.w, acc0.w);
        acc1.x = fmaf(w3, v3.x, acc1.x); acc1.y = fmaf(w3, v3.y, acc1.y);
        acc1.z = fmaf(w3, v3.z, acc1.z); acc1.w = fmaf(w3, v3.w, acc1.w);
    }
    for (; j < end; ++j) {
        int2 sw0 = __ldg(&g_sw[j]);
        float w0 = __int_as_float(sw0.y);
        float4 v0 = __ldg(sup + (size_t)sw0.x * (D_OUT / 4) + lane);
        acc0.x = fmaf(w0, v0.x, acc0.x); acc0.y = fmaf(w0, v0.y, acc0.y);
        acc0.z = fmaf(w0, v0.z, acc0.z); acc0.w = fmaf(w0, v0.w, acc0.w);
    }

    float4 bv = __ldg((const float4*)b + lane);
    float4 r;
    r.x = acc0.x + acc1.x + bv.x;
    r.y = acc0.y + acc1.y + bv.y;
    r.z = acc0.z + acc1.z + bv.z;
    r.w = acc0.w + acc1.w + bv.w;
    ((float4*)out)[(size_t)n * (D_OUT / 4) + lane] = r;
}

// ---------------------------------------------------------------------------
// Launch. Inputs: x, edge_src, edge_dst, edge_w, W, b
// ---------------------------------------------------------------------------
extern "C" void kernel_launch(void* const* d_in, const int* in_sizes, int n_in,
                              void* d_out, int out_size) {
    const float* x    = (const float*)d_in[0];
    const int*   esrc = (const int*)d_in[1];
    const int*   edst = (const int*)d_in[2];
    const float* ew   = (const float*)d_in[3];
    const float* W    = (const float*)d_in[4];
    const float* b    = (const float*)d_in[5];
    float* out = (float*)d_out;

    // GEMM into g_support
    gemm_kernel<<<(N_NODES + 127) / 128, 256>>>(x, W);

    // CSR-by-dst build
    zero_kernel<<<(N_NODES + 255) / 256, 256>>>();
    hist_kernel<<<(N_EDGES / 4 + 255) / 256, 256>>>(edst);
    scan1_kernel<<<N_SCAN_BLOCKS, SCAN_BLOCK>>>();
    scan2_kernel<<<1, 128>>>();
    scan3_kernel<<<(N_NODES + 255) / 256, 256>>>();
    place_kernel<<<(N_EDGES + 255) / 256, 256>>>(esrc, edst, ew);

    // Pull + bias (one warp per node)
    long long pull_threads = (long long)N_NODES * 32;
    pull_kernel<<<(int)((pull_threads + 255) / 256), 256>>>(b, out);
}

// round 5
// speedup vs baseline: 1.3683x; 1.1044x over previous
#include <cuda_runtime.h>
#include <cuda_bf16.h>
#include <cuda_fp16.h>
#include <cstdint>

#define N_NODES 100000
#define N_EDGES 1600000
#define D_IN    256
#define D_OUT   128

#define SCAN_BLOCK 1024
#define N_SCAN_BLOCKS ((N_NODES + SCAN_BLOCK - 1) / SCAN_BLOCK)   // 98

typedef unsigned long long ull;

// Device scratch (static __device__ arrays only; no allocation anywhere).
__device__ __half g_supph[(size_t)N_NODES * D_OUT];    // 25.6 MB (fp16 support)
__device__ int   g_count[N_NODES];
__device__ int   g_offsets[N_NODES + 1];
__device__ int   g_cursor[N_NODES];
__device__ int   g_bsum[N_SCAN_BLOCKS];
__device__ int2  g_sw[N_EDGES];                        // packed (src, bits(w))

// ---------------------------------------------------------------------------
// helpers
// ---------------------------------------------------------------------------
__device__ __forceinline__ void cp_async16(void* smem_dst, const void* gmem_src) {
    uint32_t s = (uint32_t)__cvta_generic_to_shared(smem_dst);
    asm volatile("cp.async.ca.shared.global [%0], [%1], 16;" :: "r"(s), "l"(gmem_src));
}
__device__ __forceinline__ void cp_async_commit() {
    asm volatile("cp.async.commit_group;");
}
__device__ __forceinline__ void cp_async_wait_all() {
    asm volatile("cp.async.wait_group 0;");
}
// duplicate a float into both lanes of a 64-bit f32x2 register
__device__ __forceinline__ ull pack2(float v) {
    ull r;
    asm("mov.b64 %0, {%1, %1};" : "=l"(r) : "f"(v));
    return r;
}
// d = a * b + d  on packed f32x2 (Blackwell dual-fp32 pipe)
__device__ __forceinline__ void ffma2(ull& d, ull a, ull b) {
    asm("fma.rn.f32x2 %0, %1, %2, %0;" : "+l"(d) : "l"(a), "l"(b));
}

// ---------------------------------------------------------------------------
// GEMM: support = x @ W (fp32 math via f32x2, fp16 output).
// BM=128, BN=128, BK=8, 256 threads, 8x8 reg tile, rows paired for f32x2.
// Double-buffered smem, cp.async for W, register-staged x.
// ---------------------------------------------------------------------------
__global__ __launch_bounds__(256) void gemm_kernel(const float* __restrict__ x,
                                                   const float* __restrict__ W) {
    __shared__ float As[2][8][132];    // [buf][k][row], padded; k-row = 528B (16B mult)
    __shared__ float Bs[2][8][128];    // [buf][k][col]

    const int tid = threadIdx.x;
    const int block_row = blockIdx.x * 128;
    const int tx = tid & 15;        // 16 col groups of 8
    const int ty = tid >> 4;        // 16 row groups of 8

    const int lr = tid >> 1;             // A load: row 0..127
    const int lk = (tid & 1) * 4;        // A load: k offset 0 or 4
    const int bk = tid >> 5;             // B load: k-row 0..7
    const int bc = (tid & 31) * 4;       // B load: col

    // accp[rp][c] packs output rows (ty*8+2rp, ty*8+2rp+1) for column tx*8+c
    ull accp[4][8];
#pragma unroll
    for (int rp = 0; rp < 4; ++rp)
#pragma unroll
        for (int c = 0; c < 8; ++c) accp[rp][c] = 0ull;

    const int grow = block_row + lr;
    const bool arow_ok = (grow < N_NODES);
    const float* xrow = x + (size_t)grow * D_IN;

    // ---- prologue: tile 0 ----
    float4 av = arow_ok ? __ldg((const float4*)(xrow + lk))
                        : make_float4(0.f, 0.f, 0.f, 0.f);
    cp_async16(&Bs[0][bk][bc], W + (size_t)bk * D_OUT + bc);
    cp_async_commit();
    As[0][lk + 0][lr] = av.x;
    As[0][lk + 1][lr] = av.y;
    As[0][lk + 2][lr] = av.z;
    As[0][lk + 3][lr] = av.w;
    cp_async_wait_all();
    __syncthreads();

    int buf = 0;
#pragma unroll 1
    for (int k0 = 0; k0 < D_IN; k0 += 8) {
        const int nxt = buf ^ 1;
        const bool has_next = (k0 + 8) < D_IN;
        float4 av2;
        if (has_next) {
            av2 = arow_ok ? __ldg((const float4*)(xrow + k0 + 8 + lk))
                          : make_float4(0.f, 0.f, 0.f, 0.f);
            cp_async16(&Bs[nxt][bk][bc], W + (size_t)(k0 + 8 + bk) * D_OUT + bc);
            cp_async_commit();
        }

#pragma unroll
        for (int kk = 0; kk < 8; ++kk) {
            // a-pairs: 4x 64-bit lanes straight from shared (rows ty*8 .. ty*8+7)
            longlong2 ap01 = *(const longlong2*)&As[buf][kk][ty * 8];
            longlong2 ap23 = *(const longlong2*)&As[buf][kk][ty * 8 + 4];
            ull ap[4];
            ap[0] = (ull)ap01.x; ap[1] = (ull)ap01.y;
            ap[2] = (ull)ap23.x; ap[3] = (ull)ap23.y;
            // b: 8 scalars, each duplicated into an f32x2 register (ALU pipe)
            float4 b0 = *(const float4*)&Bs[buf][kk][tx * 8];
            float4 b1 = *(const float4*)&Bs[buf][kk][tx * 8 + 4];
            ull bd[8];
            bd[0] = pack2(b0.x); bd[1] = pack2(b0.y);
            bd[2] = pack2(b0.z); bd[3] = pack2(b0.w);
            bd[4] = pack2(b1.x); bd[5] = pack2(b1.y);
            bd[6] = pack2(b1.z); bd[7] = pack2(b1.w);
#pragma unroll
            for (int rp = 0; rp < 4; ++rp)
#pragma unroll
                for (int c = 0; c < 8; ++c)
                    ffma2(accp[rp][c], ap[rp], bd[c]);
        }

        if (has_next) {
            As[nxt][lk + 0][lr] = av2.x;
            As[nxt][lk + 1][lr] = av2.y;
            As[nxt][lk + 2][lr] = av2.z;
            As[nxt][lk + 3][lr] = av2.w;
            cp_async_wait_all();
            __syncthreads();
        }
        buf = nxt;
    }

    // epilogue: unpack row pairs, convert to fp16, 16B stores
    const int r0base = block_row + ty * 8;
#pragma unroll
    for (int rp = 0; rp < 4; ++rp) {
        const int r0 = r0base + 2 * rp;
        const int r1 = r0 + 1;
        __half2 h0[4], h1[4];
#pragma unroll
        for (int i = 0; i < 4; ++i) {
            float2 va = *(float2*)&accp[rp][2 * i];      // .x = row r0, .y = row r1
            float2 vb = *(float2*)&accp[rp][2 * i + 1];
            h0[i] = __floats2half2_rn(va.x, vb.x);
            h1[i] = __floats2half2_rn(va.y, vb.y);
        }
        if (r0 < N_NODES)
            *(uint4*)(g_supph + (size_t)r0 * D_OUT + tx * 8) = *(uint4*)h0;
        if (r1 < N_NODES)
            *(uint4*)(g_supph + (size_t)r1 * D_OUT + tx * 8) = *(uint4*)h1;
    }
}

// ---------------------------------------------------------------------------
// CSR-by-dst build
// ---------------------------------------------------------------------------
__global__ void zero_kernel() {
    int i = blockIdx.x * blockDim.x + threadIdx.x;
    if (i < N_NODES) g_count[i] = 0;
}

__global__ void hist_kernel(const int* __restrict__ edst) {
    int e4 = blockIdx.x * blockDim.x + threadIdx.x;
    if (e4 < N_EDGES / 4) {
        int4 d = ((const int4*)edst)[e4];
        atomicAdd(&g_count[d.x], 1);
        atomicAdd(&g_count[d.y], 1);
        atomicAdd(&g_count[d.z], 1);
        atomicAdd(&g_count[d.w], 1);
    }
}

__global__ __launch_bounds__(SCAN_BLOCK) void scan1_kernel() {
    __shared__ int warp_sums[32];
    const int t = threadIdx.x;
    const int idx = blockIdx.x * SCAN_BLOCK + t;
    const int lane = t & 31;
    const int wrp  = t >> 5;
    int v = (idx < N_NODES) ? g_count[idx] : 0;
    int incl = v;
#pragma unroll
    for (int off = 1; off < 32; off <<= 1) {
        int n = __shfl_up_sync(0xffffffffu, incl, off);
        if (lane >= off) incl += n;
    }
    if (lane == 31) warp_sums[wrp] = incl;
    __syncthreads();
    if (t < 32) {
        int s = warp_sums[t];
        int si = s;
#pragma unroll
        for (int off = 1; off < 32; off <<= 1) {
            int n = __shfl_up_sync(0xffffffffu, si, off);
            if (t >= off) si += n;
        }
        warp_sums[t] = si - s;   // exclusive warp prefix
    }
    __syncthreads();
    int excl = incl - v + warp_sums[wrp];
    if (idx < N_NODES) g_offsets[idx] = excl;
    if (t == SCAN_BLOCK - 1) g_bsum[blockIdx.x] = excl + v;
}

__global__ void scan2_kernel() {
    __shared__ int ws[4];
    const int t = threadIdx.x;          // 128 threads
    const int lane = t & 31, wrp = t >> 5;
    int v = (t < N_SCAN_BLOCKS) ? g_bsum[t] : 0;
    int incl = v;
#pragma unroll
    for (int off = 1; off < 32; off <<= 1) {
        int n = __shfl_up_sync(0xffffffffu, incl, off);
        if (lane >= off) incl += n;
    }
    if (lane == 31) ws[wrp] = incl;
    __syncthreads();
    int add = 0;
#pragma unroll
    for (int w = 0; w < 4; ++w) add += (w < wrp) ? ws[w] : 0;
    if (t < N_SCAN_BLOCKS) g_bsum[t] = incl - v + add;   // exclusive
}

__global__ void scan3_kernel() {
    int idx = blockIdx.x * blockDim.x + threadIdx.x;
    if (idx < N_NODES) {
        int off = g_offsets[idx] + g_bsum[idx / SCAN_BLOCK];
        g_offsets[idx] = off;
        g_cursor[idx]  = off;
    }
    if (idx == 0) g_offsets[N_NODES] = N_EDGES;
}

__global__ void place_kernel(const int* __restrict__ esrc,
                             const int* __restrict__ edst,
                             const float* __restrict__ ew) {
    int e = blockIdx.x * blockDim.x + threadIdx.x;
    if (e >= N_EDGES) return;
    int d = edst[e];
    int pos = atomicAdd(&g_cursor[d], 1);
    g_sw[pos] = make_int2(esrc[e], __float_as_int(ew[e]));
}

// ---------------------------------------------------------------------------
// Pull: warp per dst node, 4 fp16 gathers in flight (8B/lane), fp32 accumulate.
// out[n] = b + sum_e w_e * support[src_e]. No atomics.
// ---------------------------------------------------------------------------
__global__ __launch_bounds__(256) void pull_kernel(const float* __restrict__ b,
                                                   float* __restrict__ out) {
    const int n    = (blockIdx.x * blockDim.x + threadIdx.x) >> 5;
    const int lane = threadIdx.x & 31;
    if (n >= N_NODES) return;

    const int start = __ldg(&g_offsets[n]);
    const int end   = __ldg(&g_offsets[n + 1]);

    float4 acc0 = make_float4(0.f, 0.f, 0.f, 0.f);
    float4 acc1 = make_float4(0.f, 0.f, 0.f, 0.f);
    const ull* sup = (const ull*)g_supph;   // 4 halves per 8B
    const int loff = lane;                  // lane's 8B chunk within a 256B row

    int j = start;
    for (; j + 3 < end; j += 4) {
        int2 sw0 = __ldg(&g_sw[j]);
        int2 sw1 = __ldg(&g_sw[j + 1]);
        int2 sw2 = __ldg(&g_sw[j + 2]);
        int2 sw3 = __ldg(&g_sw[j + 3]);
        ull u0 = __ldg(sup + (size_t)sw0.x * (D_OUT / 4) + loff);
        ull u1 = __ldg(sup + (size_t)sw1.x * (D_OUT / 4) + loff);
        ull u2 = __ldg(sup + (size_t)sw2.x * (D_OUT / 4) + loff);
        ull u3 = __ldg(sup + (size_t)sw3.x * (D_OUT / 4) + loff);
        float w0 = __int_as_float(sw0.y), w1 = __int_as_float(sw1.y);
        float w2 = __int_as_float(sw2.y), w3 = __int_as_float(sw3.y);

        float2 a0 = __half22float2(((const __half2*)&u0)[0]);
        float2 b0v = __half22float2(((const __half2*)&u0)[1]);
        float2 a1 = __half22float2(((const __half2*)&u1)[0]);
        float2 b1v = __half22float2(((const __half2*)&u1)[1]);
        float2 a2 = __half22float2(((const __half2*)&u2)[0]);
        float2 b2v = __half22float2(((const __half2*)&u2)[1]);
        float2 a3 = __half22float2(((const __half2*)&u3)[0]);
        float2 b3v = __half22float2(((const __half2*)&u3)[1]);

        acc0.x = fmaf(w0, a0.x, acc0.x); acc0.y = fmaf(w0, a0.y, acc0.y);
        acc0.z = fmaf(w0, b0v.x, acc0.z); acc0.w = fmaf(w0, b0v.y, acc0.w);
        acc1.x = fmaf(w1, a1.x, acc1.x); acc1.y = fmaf(w1, a1.y, acc1.y);
        acc1.z = fmaf(w1, b1v.x, acc1.z); acc1.w = fmaf(w1, b1v.y, acc1.w);
        acc0.x = fmaf(w2, a2.x, acc0.x); acc0.y = fmaf(w2, a2.y, acc0.y);
        acc0.z = fmaf(w2, b2v.x, acc0.z); acc0.w = fmaf(w2, b2v.y, acc0.w);
        acc1.x = fmaf(w3, a3.x, acc1.x); acc1.y = fmaf(w3, a3.y, acc1.y);
        acc1.z = fmaf(w3, b3v.x, acc1.z); acc1.w = fmaf(w3, b3v.y, acc1.w);
    }
    for (; j < end; ++j) {
        int2 sw0 = __ldg(&g_sw[j]);
        float w0 = __int_as_float(sw0.y);
        ull u0 = __ldg(sup + (size_t)sw0.x * (D_OUT / 4) + loff);
        float2 a0 = __half22float2(((const __half2*)&u0)[0]);
        float2 b0v = __half22float2(((const __half2*)&u0)[1]);
        acc0.x = fmaf(w0, a0.x, acc0.x); acc0.y = fmaf(w0, a0.y, acc0.y);
        acc0.z = fmaf(w0, b0v.x, acc0.z); acc0.w = fmaf(w0, b0v.y, acc0.w);
    }

    float4 bv = __ldg((const float4*)b + lane);
    float4 r;
    r.x = acc0.x + acc1.x + bv.x;
    r.y = acc0.y + acc1.y + bv.y;
    r.z = acc0.z + acc1.z + bv.z;
    r.w = acc0.w + acc1.w + bv.w;
    ((float4*)out)[(size_t)n * (D_OUT / 4) + lane] = r;
}

// ---------------------------------------------------------------------------
// Launch. Inputs: x, edge_src, edge_dst, edge_w, W, b
// ---------------------------------------------------------------------------
extern "C" void kernel_launch(void* const* d_in, const int* in_sizes, int n_in,
                              void* d_out, int out_size) {
    const float* x    = (const float*)d_in[0];
    const int*   esrc = (const int*)d_in[1];
    const int*   edst = (const int*)d_in[2];
    const float* ew   = (const float*)d_in[3];
    const float* W    = (const float*)d_in[4];
    const float* b    = (const float*)d_in[5];
    float* out = (float*)d_out;

    // GEMM into g_supph (fp16)
    gemm_kernel<<<(N_NODES + 127) / 128, 256>>>(x, W);

    // CSR-by-dst build
    zero_kernel<<<(N_NODES + 255) / 256, 256>>>();
    hist_kernel<<<(N_EDGES / 4 + 255) / 256, 256>>>(edst);
    scan1_kernel<<<N_SCAN_BLOCKS, SCAN_BLOCK>>>();
    scan2_kernel<<<1, 128>>>();
    scan3_kernel<<<(N_NODES + 255) / 256, 256>>>();
    place_kernel<<<(N_EDGES + 255) / 256, 256>>>(esrc, edst, ew);

    // Pull + bias (one warp per node)
    long long pull_threads = (long long)N_NODES * 32;
    pull_kernel<<<(int)((pull_threads + 255) / 256), 256>>>(b, out);
}